// round 9
// baseline (speedup 1.0000x reference)
#include <cuda_runtime.h>
#include <cstdint>

// B=4, M_IN=16, M_OUT=32, C=32.  x:(4,16,32,32,32,32) fp32 -> out:(4,32,4,32) fp32
//
//   s1[b,m,c2] = sum_{c3,c4,c5} x          (s2 == s1)
//   s3[b,m,c3] = sum_{c2,c4,c5} x
//   s4[b,m,c4] = sum_{c2,c3,c5} x
//   W = alpha+beta+gamma+delta (16x32)
//   out[b,n,i,c] = sum_m S_i[b,m,c] * W[m,n],  S = [s1,s1,s3,s4]
//
// SINGLE kernel, grid 4160:
//   bids 0..4095   : R3-proven half-slice stream. Added cost vs R3 = ONE
//                    fire-and-forget red.release.gpu.add (no return, no wait).
//   bids 4096..4159: spinner s = bid-4096 polls cnt_bm[s]==64 (acquire +
//                    nanosleep), folds bm s -> g_S, releases cnt_b[s>>4];
//                    spinners with s%16==0 then poll cnt_b==16 and run the
//                    einsum for b=s>>4. Spinners are placed LAST by the CTA
//                    scheduler -> they run in the drain wave on idle SMs.
// Counters self-reset after their last acquire -> graph-replay safe.
// Fixed FP order everywhere -> bitwise deterministic.

__device__ float g_s1h[4096];            // [bid], bid = slice*2+half, slice=(b*16+m)*32+c2
__device__ float g_s3 [2048 * 32];       // [slice][c3]  (full over c4,c5; unique owner half)
__device__ float g_s4h[4096 * 32];       // [bid][c4]    (partial over this half's c3)
__device__ float g_S  [8192];            // [bm][i][c]
__device__ int   cnt_bm[64];
__device__ int   cnt_b[4];

__device__ __forceinline__ unsigned long long addx2(unsigned long long a,
                                                    unsigned long long b) {
    unsigned long long r;
    asm("add.rn.f32x2 %0, %1, %2;" : "=l"(r) : "l"(a), "l"(b));
    return r;
}
__device__ __forceinline__ float x2sum(unsigned long long a) {
    unsigned lo, hi;
    asm("mov.b64 {%0,%1}, %2;" : "=r"(lo), "=r"(hi) : "l"(a));
    return __uint_as_float(lo) + __uint_as_float(hi);
}
// evict-first 16B streaming load (read-once data; keep L2 for partials)
__device__ __forceinline__ ulonglong2 ldcs2(const ulonglong2* p) {
    ulonglong2 r;
    asm("ld.global.cs.v2.u64 {%0, %1}, [%2];" : "=l"(r.x), "=l"(r.y) : "l"(p));
    return r;
}
// fire-and-forget release increment (REDG: no return value, no wait)
__device__ __forceinline__ void red_release(int* p) {
    asm volatile("red.release.gpu.global.add.s32 [%0], 1;" :: "l"(p) : "memory");
}
__device__ __forceinline__ int ld_acquire(const int* p) {
    int v;
    asm volatile("ld.acquire.gpu.global.s32 %0, [%1];" : "=r"(v) : "l"(p) : "memory");
    return v;
}

__global__ void __launch_bounds__(256, 4)
k_fused(const float* __restrict__ x,
        const float* __restrict__ wa, const float* __restrict__ wb,
        const float* __restrict__ wg, const float* __restrict__ wd,
        float* __restrict__ out) {
    const int t    = threadIdx.x;
    const int lane = t & 31;
    const int w    = t >> 5;
    const int bid  = blockIdx.x;

    __shared__ float s4buf[256];
    __shared__ float wt[8];
    __shared__ float pp[256];
    __shared__ float sW[512];

    if (bid < 4096) {
        // ================= stream path: R3 hot loop, verbatim =================
        const int slice = bid >> 1;
        const int half  = bid & 1;
        const ulonglong2* __restrict__ xv =
            reinterpret_cast<const ulonglong2*>(x) + (size_t)bid * 4096;

        unsigned long long col[8];
#pragma unroll
        for (int s = 0; s < 8; ++s) col[s] = 0ull;

        float rows_tot = 0.f;             // valid on lane 0
#pragma unroll
        for (int j = 0; j < 2; ++j) {
            const int k = w + j * 8;      // local row 0..15  (c3 = half*16 + k)
            const ulonglong2* __restrict__ p = xv + k * 256 + lane;

            ulonglong2 d[8];
#pragma unroll
            for (int s = 0; s < 8; ++s) d[s] = ldcs2(p + s * 32);

            unsigned long long row = 0ull;
#pragma unroll
            for (int s = 0; s < 8; ++s) {
                unsigned long long v = addx2(d[s].x, d[s].y);
                row    = addx2(row, v);
                col[s] = addx2(col[s], v);
            }
            float r = x2sum(row);
#pragma unroll
            for (int o = 16; o; o >>= 1) r += __shfl_down_sync(0xffffffffu, r, o);
            if (lane == 0) {
                g_s3[slice * 32 + half * 16 + k] = r;
                rows_tot += r;
            }
        }

#pragma unroll
        for (int s = 0; s < 8; ++s) {
            float cs = x2sum(col[s]);
            cs += __shfl_down_sync(0xffffffffu, cs, 4);
            cs += __shfl_down_sync(0xffffffffu, cs, 2);
            cs += __shfl_down_sync(0xffffffffu, cs, 1);
            if ((lane & 7) == 0) s4buf[w * 32 + s * 4 + (lane >> 3)] = cs;
        }
        if (lane == 0) wt[w] = rows_tot;
        __syncthreads();

        if (t < 32) {
            float v = 0.f;
#pragma unroll
            for (int ww = 0; ww < 8; ++ww) v += s4buf[ww * 32 + t];
            g_s4h[bid * 32 + t] = v;
            if (t == 0) {
                float s = 0.f;
#pragma unroll
                for (int ww = 0; ww < 8; ++ww) s += wt[ww];
                g_s1h[bid] = s;
            }
            __syncwarp();
            // fire-and-forget completion signal: no latency on critical path
            if (t == 0) red_release(&cnt_bm[bid >> 6]);
        }
        return;
    }

    // ================= spinner path: s = bid - 4096 =================
    const int s  = bid - 4096;            // 0..63 == bm
    const int bm = s;
    const bool is_einsum = (s & 15) == 0;
    const int  b = s >> 4;

    // preload W while waiting (independent of stream results)
    if (is_einsum) {
        sW[t]       = wa[t]       + wb[t]       + wg[t]       + wd[t];
        sW[t + 256] = wa[t + 256] + wb[t + 256] + wg[t + 256] + wd[t + 256];
    }

    // ---- wait for this bm's 64 stream blocks ----
    if (t == 0) {
        while (ld_acquire(&cnt_bm[bm]) != 64) __nanosleep(128);
        cnt_bm[bm] = 0;                   // self-reset for next graph replay
    }
    __syncthreads();

    // ---- fold bm -> g_S[bm][i][c] (fixed order, deterministic) ----
    {
        float v = 0.f;
        if (t < 32) {
            v = g_s1h[(bm * 32 + t) * 2] + g_s1h[(bm * 32 + t) * 2 + 1];
        } else if (t >= 64 && t < 128) {
            const int c3 = (t - 64) & 31, part = (t - 64) >> 5;
            const float* __restrict__ p = g_s3 + bm * 1024 + part * 512 + c3;
#pragma unroll
            for (int q = 0; q < 16; ++q) v += p[q * 32];      // over c2
        } else if (t >= 128) {
            const int c4 = (t - 128) & 31, part = (t - 128) >> 5;
            const float* __restrict__ p = g_s4h + (bm * 64 + part * 16) * 32 + c4;
#pragma unroll
            for (int q = 0; q < 16; ++q) v += p[q * 32];      // over (c2,half)
        }
        pp[t] = v;
    }
    __syncthreads();
    if (t < 32) {
        const float s1v = pp[t];
        const float s3v = pp[64 + t] + pp[96 + t];
        const float s4v = pp[128 + t] + pp[160 + t] + pp[192 + t] + pp[224 + t];
        g_S[bm * 128 +       t] = s1v;
        g_S[bm * 128 +  32 + t] = s1v;
        g_S[bm * 128 +  64 + t] = s3v;
        g_S[bm * 128 +  96 + t] = s4v;
        __syncwarp();
        if (t == 0) red_release(&cnt_b[b]);
    }

    if (!is_einsum) return;

    // ---- einsum spinner: wait for the 16 folds of this b ----
    if (t == 0) {
        while (ld_acquire(&cnt_b[b]) != 16) __nanosleep(128);
        cnt_b[b] = 0;                     // self-reset
    }
    __syncthreads();

    {
        const int combo = t >> 1;         // (i, c)
        const int nh    = t & 1;
        const int i = combo >> 5;
        const int c = combo & 31;
        float S[16];
#pragma unroll
        for (int m = 0; m < 16; ++m) S[m] = g_S[(b * 16 + m) * 128 + i * 32 + c];
#pragma unroll
        for (int n0 = 0; n0 < 16; ++n0) {
            const int n = nh * 16 + n0;
            float acc = 0.f;
#pragma unroll
            for (int m = 0; m < 16; ++m) acc += S[m] * sW[m * 32 + n];
            out[((b * 32 + n) * 4 + i) * 32 + c] = acc;
        }
    }
}

// ---------------- launch ----------------
extern "C" void kernel_launch(void* const* d_in, const int* in_sizes, int n_in,
                              void* d_out, int out_size) {
    const float* x     = (const float*)d_in[0];
    const float* alpha = (const float*)d_in[1];
    const float* beta  = (const float*)d_in[2];
    const float* gamma = (const float*)d_in[3];
    const float* delta = (const float*)d_in[4];

    k_fused<<<4160, 256>>>(x, alpha, beta, gamma, delta, (float*)d_out);
}

// round 10
// speedup vs baseline: 1.0629x; 1.0629x over previous
#include <cuda_runtime.h>
#include <cstdint>

// B=4, M_IN=16, M_OUT=32, C=32.  x:(4,16,32,32,32,32) fp32 -> out:(4,32,4,32) fp32
//
//   s1[b,m,c2] = sum_{c3,c4,c5} x          (s2 == s1)
//   s3[b,m,c3] = sum_{c2,c4,c5} x
//   s4[b,m,c4] = sum_{c2,c3,c5} x
//   W = alpha+beta+gamma+delta (16x32)
//   out[b,n,i,c] = sum_m S_i[b,m,c] * W[m,n],  S = [s1,s1,s3,s4]
//
// Kernel 1 (4096 blocks): R3-proven half-slice stream. Epilogue now
//   REDG-accumulates directly into g_S[bm][i][c] (~50 fire-and-forget
//   red.global.add.f32 per block; no partial arrays, no tail stage A).
// Kernel 2 (16 blocks, (b,i)): pure einsum from L2-hot g_S; snapshots S to
//   smem, self-zeros g_S for the next graph replay, computes 1024 outputs.
// g_S is zero at module load; every einsum call re-zeros it -> replay-safe.

__device__ float g_S[8192];              // [bm][i][c], REDG-accumulated

__device__ __forceinline__ unsigned long long addx2(unsigned long long a,
                                                    unsigned long long b) {
    unsigned long long r;
    asm("add.rn.f32x2 %0, %1, %2;" : "=l"(r) : "l"(a), "l"(b));
    return r;
}
__device__ __forceinline__ float x2sum(unsigned long long a) {
    unsigned lo, hi;
    asm("mov.b64 {%0,%1}, %2;" : "=r"(lo), "=r"(hi) : "l"(a));
    return __uint_as_float(lo) + __uint_as_float(hi);
}
// evict-first 16B streaming load (read-once data; keep L2 for partials)
__device__ __forceinline__ ulonglong2 ldcs2(const ulonglong2* p) {
    ulonglong2 r;
    asm("ld.global.cs.v2.u64 {%0, %1}, [%2];" : "=l"(r.x), "=l"(r.y) : "l"(p));
    return r;
}
// fire-and-forget float accumulate (REDG: no return, no wait)
__device__ __forceinline__ void red_add(float* p, float v) {
    asm volatile("red.global.add.f32 [%0], %1;" :: "l"(p), "f"(v) : "memory");
}

// ---------------- Kernel 1: half-slice reduction (R3 hot loop) + REDG epilogue ------------
__global__ void __launch_bounds__(256, 4)
k_reduce(const float* __restrict__ x) {
    const int t    = threadIdx.x;
    const int lane = t & 31;
    const int w    = t >> 5;
    const int bid  = blockIdx.x;          // half-slice id
    const int slice = bid >> 1;
    const int half  = bid & 1;
    const int bm    = bid >> 6;

    const ulonglong2* __restrict__ xv =
        reinterpret_cast<const ulonglong2*>(x) + (size_t)bid * 4096; // 16384 floats

    __shared__ float s4buf[256];          // [warp][c4]
    __shared__ float wt[8];

    unsigned long long col[8];
#pragma unroll
    for (int s = 0; s < 8; ++s) col[s] = 0ull;

    float rows_tot = 0.f;                 // valid on lane 0
#pragma unroll
    for (int j = 0; j < 2; ++j) {
        const int k = w + j * 8;          // local row 0..15  (c3 = half*16 + k)
        const ulonglong2* __restrict__ p = xv + k * 256 + lane;

        ulonglong2 d[8];
#pragma unroll
        for (int s = 0; s < 8; ++s) d[s] = ldcs2(p + s * 32);   // 8 back-to-back LDG.128

        unsigned long long row = 0ull;
#pragma unroll
        for (int s = 0; s < 8; ++s) {
            unsigned long long v = addx2(d[s].x, d[s].y);  // {f0+f2, f1+f3}
            row    = addx2(row, v);
            col[s] = addx2(col[s], v);
        }
        float r = x2sum(row);
#pragma unroll
        for (int o = 16; o; o >>= 1) r += __shfl_down_sync(0xffffffffu, r, o);
        if (lane == 0) {
            // s3 contribution for c3 = half*16+k (32 contributors over c2)
            red_add(&g_S[bm * 128 + 64 + half * 16 + k], r);
            rows_tot += r;
        }
    }

    // fold column accs: lanes in an octet share c4 = s*4 + (lane>>3)
#pragma unroll
    for (int s = 0; s < 8; ++s) {
        float cs = x2sum(col[s]);
        cs += __shfl_down_sync(0xffffffffu, cs, 4);
        cs += __shfl_down_sync(0xffffffffu, cs, 2);
        cs += __shfl_down_sync(0xffffffffu, cs, 1);
        if ((lane & 7) == 0) s4buf[w * 32 + s * 4 + (lane >> 3)] = cs;
    }
    if (lane == 0) wt[w] = rows_tot;
    __syncthreads();

    if (t < 32) {        // warp 0: cross-warp s4 fold -> REDG; block total -> s1 (i=0,1)
        float v = 0.f;
#pragma unroll
        for (int ww = 0; ww < 8; ++ww) v += s4buf[ww * 32 + t];
        red_add(&g_S[bm * 128 + 96 + t], v);            // s4[c4=t], 64 contributors
        if (t == 0) {
            float s = 0.f;
#pragma unroll
            for (int ww = 0; ww < 8; ++ww) s += wt[ww];
            const int c2 = (slice & 31);
            red_add(&g_S[bm * 128 +      c2], s);       // s1[c2], 2 contributors
            red_add(&g_S[bm * 128 + 32 + c2], s);       // s2 == s1
        }
    }
}

// ---------------- Kernel 2: pure einsum, grid 16 = (b,i), self-zeroing ----------------
__global__ void __launch_bounds__(256)
k_einsum(const float* __restrict__ a, const float* __restrict__ bb,
         const float* __restrict__ g, const float* __restrict__ d,
         float* __restrict__ out) {
    __shared__ float sS[512];             // [m][c] for this (b,i)
    __shared__ float sW[512];             // [m][n]

    const int t   = threadIdx.x;
    const int bid = blockIdx.x;
    const int b   = bid >> 2;
    const int i   = bid & 3;

    sW[t]       = a[t]       + bb[t]       + g[t]       + d[t];
    sW[t + 256] = a[t + 256] + bb[t + 256] + g[t + 256] + d[t + 256];

    // snapshot S[b, m, i, c] -> smem (2 values per thread)
    const int e0 = t, e1 = t + 256;       // e = m*32 + c
    float* p0 = &g_S[(b * 16 + (e0 >> 5)) * 128 + i * 32 + (e0 & 31)];
    float* p1 = &g_S[(b * 16 + (e1 >> 5)) * 128 + i * 32 + (e1 & 31)];
    sS[e0] = *p0;
    sS[e1] = *p1;
    __syncthreads();

    // self-zero for the next graph replay (reads are snapshotted above)
    *p0 = 0.f;
    *p1 = 0.f;

    // thread computes 4 outputs: c = t&31, n = (t>>5) + 8*nn
    const int c  = t & 31;
    const int n0 = t >> 5;
#pragma unroll
    for (int nn = 0; nn < 4; ++nn) {
        const int n = n0 + 8 * nn;
        float acc = 0.f;
#pragma unroll
        for (int m = 0; m < 16; ++m)
            acc += sS[m * 32 + c] * sW[m * 32 + n];
        out[((b * 32 + n) * 4 + i) * 32 + c] = acc;
    }
}

// ---------------- launch ----------------
extern "C" void kernel_launch(void* const* d_in, const int* in_sizes, int n_in,
                              void* d_out, int out_size) {
    const float* x     = (const float*)d_in[0];
    const float* alpha = (const float*)d_in[1];
    const float* beta  = (const float*)d_in[2];
    const float* gamma = (const float*)d_in[3];
    const float* delta = (const float*)d_in[4];

    k_reduce<<<4096, 256>>>(x);
    k_einsum<<<16, 256>>>(alpha, beta, gamma, delta, (float*)d_out);
}